// round 17
// baseline (speedup 1.0000x reference)
#include <cuda_runtime.h>
#include <cuda_bf16.h>
#include <math.h>
#include <stdint.h>

#define Nn 20000
#define Cc 256
#define Ee 100000
#define RC 4
#define NB 79     // scan blocks: 79*256 = 20224 >= Nn
#define DEGC 64   // edge chunk per staging pass

// ---------------- device scratch ----------------
__device__ float g_xl[RC * Nn * Cc];
__device__ int   g_cnt[Nn];
__device__ int   g_seg[Nn + 1];
__device__ int   g_cursor[Nn];
__device__ int   g_sorted[Ee];
__device__ int   g_bsum[NB];
__device__ int   g_boff[NB];
// Pre-swizzled bf16 operand images. Each (row-block, kb) unit = 32768 bytes:
// hi image (128x64, SW128) at +0, lo image at +16384.
__device__ __nv_bfloat16 g_Ax[625 * 4 * 2 * 8192];     // x converted
__device__ __nv_bfloat16 g_Asum[625 * 4 * 2 * 8192];   // scatter-mean converted
__device__ __nv_bfloat16 g_B1[4 * 2 * 2 * 8192];       // lin_W
__device__ __nv_bfloat16 g_B2[8 * 2 * 2 * 8192];       // linl_W | linr_W

__device__ __forceinline__ uint32_t smem_u32(const void* p) {
    uint32_t a;
    asm("{ .reg .u64 t; cvta.to.shared.u64 t, %1; cvt.u32.u64 %0, t; }" : "=r"(a) : "l"(p));
    return a;
}
__host__ __device__ __forceinline__ uint32_t SWZ(uint32_t off) { return off ^ ((off >> 3) & 0x70); }

__device__ __forceinline__ void ldsm4(uint32_t& r0, uint32_t& r1, uint32_t& r2, uint32_t& r3,
                                      uint32_t addr) {
    asm volatile("ldmatrix.sync.aligned.m8n8.x4.shared.b16 {%0,%1,%2,%3}, [%4];"
                 : "=r"(r0), "=r"(r1), "=r"(r2), "=r"(r3) : "r"(addr));
}
__device__ __forceinline__ void mma16816(float* c, const uint32_t* a, uint32_t b0, uint32_t b1) {
    asm volatile(
        "mma.sync.aligned.m16n8k16.row.col.f32.bf16.bf16.f32 "
        "{%0,%1,%2,%3}, {%4,%5,%6,%7}, {%8,%9}, {%0,%1,%2,%3};"
        : "+f"(c[0]), "+f"(c[1]), "+f"(c[2]), "+f"(c[3])
        : "r"(a[0]), "r"(a[1]), "r"(a[2]), "r"(a[3]), "r"(b0), "r"(b1));
}
__device__ __forceinline__ void cp16(uint32_t dst, const void* src) {
    asm volatile("cp.async.cg.shared.global [%0], [%1], 16;" :: "r"(dst), "l"(src));
}
__device__ __forceinline__ void split_bf16(float v, unsigned short& h, unsigned short& l) {
    __nv_bfloat16 hb = __float2bfloat16(v);
    __nv_bfloat16 lb = __float2bfloat16(v - __bfloat162float(hb));
    h = *(unsigned short*)&hb;
    l = *(unsigned short*)&lb;
}

// ---------------- conversion / prep kernels ----------------
__global__ void conv_x(const float* __restrict__ x) {
    int idx = blockIdx.x * 256 + threadIdx.x;
    int m = idx >> 6, q = idx & 63;
    float4 v = *(const float4*)(x + (size_t)m * 256 + q * 4);
    unsigned short h0, h1, h2, h3, l0, l1, l2, l3;
    split_bf16(v.x, h0, l0); split_bf16(v.y, h1, l1);
    split_bf16(v.z, h2, l2); split_bf16(v.w, h3, l3);
    uint2 hp = make_uint2((uint32_t)h0 | ((uint32_t)h1 << 16), (uint32_t)h2 | ((uint32_t)h3 << 16));
    uint2 lp = make_uint2((uint32_t)l0 | ((uint32_t)l1 << 16), (uint32_t)l2 | ((uint32_t)l3 << 16));
    int kb = q >> 4, qq = q & 15;
    char* base = (char*)g_Ax + ((size_t)((m >> 7) * 4 + kb)) * 32768;
    uint32_t off = SWZ((uint32_t)((m & 127) * 128 + qq * 8));
    *(uint2*)(base + off) = hp;
    *(uint2*)(base + 16384 + off) = lp;
}

__global__ void prep_weights(const float* __restrict__ lin_W, const float* __restrict__ linl_W,
                             const float* __restrict__ linr_W) {
    int idx = blockIdx.x * blockDim.x + threadIdx.x;
    if (idx >= 3 * 65536) return;
    int m = idx >> 16;
    int kn = idx & 65535;
    int k = kn >> 8, n = kn & 255;
    const float* W = (m == 0) ? lin_W : ((m == 1) ? linl_W : linr_W);
    float v = W[k * 256 + n];
    __nv_bfloat16 hb = __float2bfloat16(v);
    __nv_bfloat16 lb = __float2bfloat16(v - __bfloat162float(hb));
    int h = n >> 7, np = n & 127, kb = k >> 6, kc = k & 63;
    uint32_t elem = SWZ((uint32_t)(np * 128 + kc * 2)) >> 1;
    if (m == 0) {
        size_t base = ((size_t)(kb * 2 + h) * 2) * 8192;
        g_B1[base + elem] = hb;
        g_B1[base + 8192 + elem] = lb;
    } else {
        int kb2 = (m == 1) ? kb : kb + 4;
        size_t base = ((size_t)(kb2 * 2 + h) * 2) * 8192;
        g_B2[base + elem] = hb;
        g_B2[base + 8192 + elem] = lb;
    }
}

__global__ void zero_cnt() {
    int n = blockIdx.x * blockDim.x + threadIdx.x;
    if (n < Nn) g_cnt[n] = 0;
}
__global__ void count_kernel(const int* __restrict__ ei) {
    int e = blockIdx.x * blockDim.x + threadIdx.x;
    if (e < Ee) atomicAdd(&g_cnt[ei[Ee + e]], 1);
}
__global__ void bsum_kernel() {
    __shared__ int ws[8];
    int idx = blockIdx.x * 256 + threadIdx.x;
    int v = (idx < Nn) ? g_cnt[idx] : 0;
    int s = v;
#pragma unroll
    for (int o = 16; o > 0; o >>= 1) s += __shfl_down_sync(0xffffffffu, s, o);
    if ((threadIdx.x & 31) == 0) ws[threadIdx.x >> 5] = s;
    __syncthreads();
    if (threadIdx.x == 0) {
        int t = 0;
#pragma unroll
        for (int i = 0; i < 8; i++) t += ws[i];
        g_bsum[blockIdx.x] = t;
    }
}
// parallel scan of NB block sums (1 block, 128 threads)
__global__ void bscan_kernel() {
    __shared__ int s[128];
    int t = threadIdx.x;
    int v = (t < NB) ? g_bsum[t] : 0;
    s[t] = v;
    __syncthreads();
#pragma unroll
    for (int o = 1; o < 128; o <<= 1) {
        int nv = (t >= o) ? s[t - o] : 0;
        __syncthreads();
        s[t] += nv;
        __syncthreads();
    }
    if (t < NB) g_boff[t] = s[t] - v;          // exclusive
    if (t == NB - 1) g_seg[Nn] = s[t];
}
__global__ void seg_kernel() {
    __shared__ int s[256];
    int t = threadIdx.x;
    int idx = blockIdx.x * 256 + t;
    int v = (idx < Nn) ? g_cnt[idx] : 0;
    s[t] = v;
    __syncthreads();
#pragma unroll
    for (int o = 1; o < 256; o <<= 1) {
        int nv = (t >= o) ? s[t - o] : 0;
        __syncthreads();
        s[t] += nv;
        __syncthreads();
    }
    if (idx < Nn) {
        g_seg[idx] = g_boff[blockIdx.x] + s[t] - v;
        g_cursor[idx] = 0;
    }
}
__global__ void scatter_kernel(const int* __restrict__ ei) {
    int e = blockIdx.x * blockDim.x + threadIdx.x;
    if (e < Ee) {
        int d = ei[Ee + e];
        int pos = g_seg[d] + atomicAdd(&g_cursor[d], 1);
        g_sorted[pos] = e;
    }
}

// ---------------- pure-MMA GEMM, pass-structured MMA scheduling ----------------
__global__ __launch_bounds__(256, 2)
void mm_gemm(const float* __restrict__ bias, float* __restrict__ Out, int KB, int mode) {
    extern __shared__ __align__(1024) char smem[];
    int tid = threadIdx.x, lane = tid & 31, wid = tid >> 5;
    int warp_m = wid & 3, warp_n = wid >> 2;
    int h = blockIdx.x, br = blockIdx.y;

    const __nv_bfloat16* Bimg = mode ? g_B2 : g_B1;
    float* dst = mode ? Out : g_xl;
    uint32_t sbase = smem_u32(smem);

    auto asrc = [&](int kb) -> const char* {
        if (mode == 1 && kb < 4)
            return (const char*)g_Asum + ((size_t)(br * 4 + kb)) * 32768;
        int kk = mode ? kb - 4 : kb;
        return (const char*)g_Ax + ((size_t)(br * 4 + kk)) * 32768;
    };

    float acc[2][8][4] = {};

    {
        const uint4* ap = (const uint4*)asrc(0);
        for (int i = tid; i < 2048; i += 256) cp16(sbase + i * 16, ap + i);
        asm volatile("cp.async.commit_group;");
        const uint4* bp = (const uint4*)(Bimg + ((size_t)(0 * 2 + h) * 2) * 8192);
        for (int i = tid; i < 2048; i += 256) cp16(sbase + 65536 + i * 16, bp + i);
        asm volatile("cp.async.commit_group;");
    }

    for (int kb = 0; kb < KB; kb++) {
        uint32_t sA = sbase + (kb & 1) * 32768;
        uint32_t sB = sbase + 65536;
        if (kb + 1 < KB) {
            uint32_t sAn = sbase + ((kb + 1) & 1) * 32768;
            const uint4* ap = (const uint4*)asrc(kb + 1);
            for (int i = tid; i < 2048; i += 256) cp16(sAn + i * 16, ap + i);
            asm volatile("cp.async.commit_group;");
            asm volatile("cp.async.wait_group 1;" ::: "memory");
        } else {
            asm volatile("cp.async.wait_group 0;" ::: "memory");
        }
        __syncthreads();

#pragma unroll
        for (int ks = 0; ks < 4; ks++) {
            int koff = ks * 32 + ((lane >> 4) * 16);
            uint32_t ahi[2][4], alo[2][4], bh[4][4], bl[4][4];
#pragma unroll
            for (int mf = 0; mf < 2; mf++) {
                int row = warp_m * 32 + mf * 16 + (lane & 15);
                uint32_t off = SWZ((uint32_t)(row * 128 + koff));
                ldsm4(ahi[mf][0], ahi[mf][1], ahi[mf][2], ahi[mf][3], sA + off);
                ldsm4(alo[mf][0], alo[mf][1], alo[mf][2], alo[mf][3], sA + 16384 + off);
            }
#pragma unroll
            for (int np = 0; np < 4; np++) {
                int n = warp_n * 64 + np * 16 + (lane & 15);
                uint32_t off = SWZ((uint32_t)(n * 128 + koff));
                ldsm4(bh[np][0], bh[np][1], bh[np][2], bh[np][3], sB + off);
                ldsm4(bl[np][0], bl[np][1], bl[np][2], bl[np][3], sB + 16384 + off);
            }
            // pass 1: hi·hi — 16 independent MMAs
#pragma unroll
            for (int np = 0; np < 4; np++)
#pragma unroll
                for (int mf = 0; mf < 2; mf++) {
                    mma16816(acc[mf][np * 2],     ahi[mf], bh[np][0], bh[np][2]);
                    mma16816(acc[mf][np * 2 + 1], ahi[mf], bh[np][1], bh[np][3]);
                }
            // pass 2: hi·lo
#pragma unroll
            for (int np = 0; np < 4; np++)
#pragma unroll
                for (int mf = 0; mf < 2; mf++) {
                    mma16816(acc[mf][np * 2],     ahi[mf], bl[np][0], bl[np][2]);
                    mma16816(acc[mf][np * 2 + 1], ahi[mf], bl[np][1], bl[np][3]);
                }
            // pass 3: lo·hi
#pragma unroll
            for (int np = 0; np < 4; np++)
#pragma unroll
                for (int mf = 0; mf < 2; mf++) {
                    mma16816(acc[mf][np * 2],     alo[mf], bh[np][0], bh[np][2]);
                    mma16816(acc[mf][np * 2 + 1], alo[mf], bh[np][1], bh[np][3]);
                }
        }
        __syncthreads();
        if (kb + 1 < KB) {
            const uint4* bp = (const uint4*)(Bimg + ((size_t)((kb + 1) * 2 + h) * 2) * 8192);
            for (int i = tid; i < 2048; i += 256) cp16(sB + i * 16, bp + i);
            asm volatile("cp.async.commit_group;");
        }
    }

    int gid = lane >> 2, tig = lane & 3;
#pragma unroll
    for (int mf = 0; mf < 2; mf++) {
#pragma unroll
        for (int nf = 0; nf < 8; nf++) {
            int col = h * 128 + warp_n * 64 + nf * 8 + tig * 2;
            float2 bv = *(const float2*)(bias + col);
            int row0 = br * 128 + warp_m * 32 + mf * 16 + gid;
            float* c = acc[mf][nf];
            *(float2*)(dst + (size_t)row0 * 256 + col) = make_float2(c[0] + bv.x, c[1] + bv.y);
            *(float2*)(dst + (size_t)(row0 + 8) * 256 + col) = make_float2(c[2] + bv.x, c[3] + bv.y);
        }
    }
}

// ---------------- sorted message kernel: smem-staged edge metadata ----------------
__global__ __launch_bounds__(256)
void msg_sorted(const float* __restrict__ edge_attr,
                const float* __restrict__ edge_weight,
                const float* __restrict__ bond_W,
                const float* __restrict__ bond_b,
                const int* __restrict__ ei) {
    __shared__ int   s_e[DEGC];
    __shared__ int   s_src[DEGC];
    __shared__ float s_w[4][DEGC];
    __shared__ float s_attr[DEGC][16];
    int d = blockIdx.x;
    int c = threadIdx.x;
    int s0 = g_seg[d], s1 = g_seg[d + 1];
    int deg = s1 - s0;
    float bw[16];
#pragma unroll
    for (int k = 0; k < 16; k++) bw[k] = __ldg(&bond_W[k * 256 + c]);
    float bb = __ldg(&bond_b[c]);
    float acc0 = 0.f, acc1 = 0.f, acc2 = 0.f, acc3 = 0.f;

    for (int base = 0; base < deg; base += DEGC) {
        int nb = min(DEGC, deg - base);
        __syncthreads();
        if (c < nb) {
            int e = g_sorted[s0 + base + c];
            s_e[c] = e;
            s_src[c] = __ldg(&ei[e]);
            s_w[0][c] = __ldg(&edge_weight[e]);
            s_w[1][c] = __ldg(&edge_weight[Ee + e]);
            s_w[2][c] = __ldg(&edge_weight[2 * Ee + e]);
            s_w[3][c] = __ldg(&edge_weight[3 * Ee + e]);
        }
        __syncthreads();
        for (int i = c; i < nb * 4; i += 256) {
            int j = i >> 2, q = i & 3;
            float4 a = __ldg((const float4*)(edge_attr + (size_t)s_e[j] * 16) + q);
            s_attr[j][q * 4 + 0] = a.x;
            s_attr[j][q * 4 + 1] = a.y;
            s_attr[j][q * 4 + 2] = a.z;
            s_attr[j][q * 4 + 3] = a.w;
        }
        __syncthreads();
#pragma unroll 4
        for (int j = 0; j < nb; j++) {
            int s = s_src[j];
            const float* xr = g_xl + (size_t)s * 256 + c;
            float x0 = xr[0];
            float x1 = xr[(size_t)Nn * 256];
            float x2 = xr[(size_t)2 * Nn * 256];
            float x3 = xr[(size_t)3 * Nn * 256];
            float emb = bb;
#pragma unroll
            for (int k = 0; k < 16; k++) emb = fmaf(s_attr[j][k], bw[k], emb);
            float v0 = x0 + emb, v1 = x1 + emb, v2 = x2 + emb, v3 = x3 + emb;
            acc0 += 0.5f * v0 * (1.0f + erff(v0 * 0.70710678118654752f)) * s_w[0][j];
            acc1 += 0.5f * v1 * (1.0f + erff(v1 * 0.70710678118654752f)) * s_w[1][j];
            acc2 += 0.5f * v2 * (1.0f + erff(v2 * 0.70710678118654752f)) * s_w[2][j];
            acc3 += 0.5f * v3 * (1.0f + erff(v3 * 0.70710678118654752f)) * s_w[3][j];
        }
    }

    float inv = 1.0f / (float)max(deg, 1);
    float vals[4] = {acc0 * inv, acc1 * inv, acc2 * inv, acc3 * inv};
    int kb = c >> 6, kc = c & 63;
#pragma unroll
    for (int rc = 0; rc < 4; rc++) {
        int m = rc * Nn + d;
        char* base = (char*)g_Asum + ((size_t)((m >> 7) * 4 + kb)) * 32768;
        uint32_t off = SWZ((uint32_t)((m & 127) * 128 + kc * 2));
        unsigned short hb, lb;
        split_bf16(vals[rc], hb, lb);
        *(unsigned short*)(base + off) = hb;
        *(unsigned short*)(base + 16384 + off) = lb;
    }
}

// ---------------------------------------------------------------------------
extern "C" void kernel_launch(void* const* d_in, const int* in_sizes, int n_in,
                              void* d_out, int out_size) {
    const float* x           = (const float*)d_in[0];
    const float* edge_attr   = (const float*)d_in[1];
    const float* edge_weight = (const float*)d_in[2];
    const float* lin_W       = (const float*)d_in[3];
    const float* lin_b       = (const float*)d_in[4];
    const float* linl_W      = (const float*)d_in[5];
    const float* linl_b      = (const float*)d_in[6];
    const float* linr_W      = (const float*)d_in[7];
    const float* bond_W      = (const float*)d_in[8];
    const float* bond_b      = (const float*)d_in[9];
    const int*   ei          = (const int*)d_in[10];
    float* out = (float*)d_out;

    const int SMEM_BYTES = 96 * 1024;
    cudaFuncSetAttribute(mm_gemm, cudaFuncAttributeMaxDynamicSharedMemorySize, SMEM_BYTES);

    zero_cnt<<<(Nn + 255) / 256, 256>>>();                       // 0
    conv_x<<<20000, 256>>>(x);                                   // 1
    prep_weights<<<768, 256>>>(lin_W, linl_W, linr_W);           // 2
    mm_gemm<<<dim3(2, 625), 256, SMEM_BYTES>>>(lin_b, nullptr, 4, 0);   // 3 <- profiled
    count_kernel<<<(Ee + 255) / 256, 256>>>(ei);                 // 4
    bsum_kernel<<<NB, 256>>>();                                  // 5
    bscan_kernel<<<1, 128>>>();                                  // 6
    seg_kernel<<<NB, 256>>>();                                   // 7
    scatter_kernel<<<(Ee + 255) / 256, 256>>>(ei);               // 8
    msg_sorted<<<Nn, 256>>>(edge_attr, edge_weight, bond_W, bond_b, ei); // 9
    mm_gemm<<<dim3(2, 625), 256, SMEM_BYTES>>>(linl_b, out, 8, 1);       // 10
}